// round 11
// baseline (speedup 1.0000x reference)
#include <cuda_runtime.h>
#include <cuda_bf16.h>
#include <cstdint>

// RootMLP: per-sample MLP 1 -> 128 -> 128 -> 128 -> 128 -> 64 (SiLU between),
// head: mean=tanh(z[0:32]), std=exp(0.5*clip(z[32:64],-4,4)), out=[mean,std].
// Each of 4096 batch elements has its own 58048 flat fp32 params:
//   W0[128x1]@0, b0[128]@128, W1[128x128]@256, b1@16640,
//   W2@16768, b2@33152, W3@33280, b3@49664, W4[64x128]@49792, b4[64]@57984.
// HBM-bound: 951 MB weight read, once -> ~120us floor. Strategy: persistent
// blocks, cp.async double-buffered smem staging, padded rows (conflict-free
// LDS.128), broadcast activation reads, cross-element prefetch.

#define BATCH      4096
#define TP         58048   // total params per element
#define PADROW     132     // padded row floats (33 16B units, odd -> conflict-free)
#define WBUF_FLTS  (128 * PADROW)   // 16896
#define ABUF_FLTS  (WBUF_FLTS + 128)

__device__ __forceinline__ void cp16(float* dst_smem, const float* src_gmem) {
    uint32_t d = (uint32_t)__cvta_generic_to_shared(dst_smem);
    asm volatile("cp.async.cg.shared.global [%0], [%1], 16;\n"
                 :: "r"(d), "l"(src_gmem) : "memory");
}
__device__ __forceinline__ void cp_commit() {
    asm volatile("cp.async.commit_group;\n" ::: "memory");
}
template <int N>
__device__ __forceinline__ void cp_wait() {
    asm volatile("cp.async.wait_group %0;\n" :: "n"(N) : "memory");
}

// Stage a layer's weights (R rows x 128 cols) + bias into padded smem.
template <int R>
__device__ __forceinline__ void load_stage(float* Wdst, float* bdst,
                                           const float* wp, int wOff, int bOff,
                                           int t) {
    // R*32 16B chunks; one warp covers one row of 32 chunks -> 512B/instr coalesced
    #pragma unroll
    for (int c = t; c < R * 32; c += 128) {
        int r = c >> 5, cc = c & 31;
        cp16(Wdst + (r * PADROW + cc * 4), wp + wOff + c * 4);
    }
    if (t < (R >> 2))
        cp16(bdst + t * 4, wp + bOff + t * 4);
}

// Thread t computes output row t (t < R) from 128 smem activations.
template <int R>
__device__ __forceinline__ float dense_row(const float* Wb, const float* bias,
                                           const float* ysm, int t) {
    const float4* Wr  = reinterpret_cast<const float4*>(Wb + t * PADROW);
    const float4* yv4 = reinterpret_cast<const float4*>(ysm);
    float a0 = 0.f, a1 = 0.f, a2 = 0.f, a3 = 0.f;
    #pragma unroll
    for (int i = 0; i < 32; i++) {
        float4 w = Wr[i];          // conflict-free LDS.128 (odd 16B-unit stride)
        float4 v = yv4[i];         // broadcast LDS.128 (1 wavefront)
        a0 = fmaf(w.x, v.x, a0);
        a1 = fmaf(w.y, v.y, a1);
        a2 = fmaf(w.z, v.z, a2);
        a3 = fmaf(w.w, v.w, a3);
    }
    return ((a0 + a1) + (a2 + a3)) + bias[t];
}

__device__ __forceinline__ float silu(float z) {
    return z / (1.0f + __expf(-z));
}

__global__ void __launch_bounds__(128, 1)
rootmlp_kernel(const float* __restrict__ x,
               const float* __restrict__ fw,
               float* __restrict__ out,
               int gridStride) {
    extern __shared__ float sm[];
    float* S  = sm;                       // 256: layer-0 W0+b0
    float* y  = sm + 256;                 // 128: activations
    float* A  = sm + 384;                 // buffer A
    float* Ab = A + WBUF_FLTS;
    float* Bf = sm + 384 + ABUF_FLTS;     // buffer B
    float* Bb = Bf + WBUF_FLTS;

    const int t = threadIdx.x;
    int e = blockIdx.x;
    if (e >= BATCH) return;
    const float* wp = fw + (size_t)e * TP;

    // Prologue: s0(e), s1(e)->A, s2(e)->B  (3 groups pending at loop top)
    if (t < 64) cp16(S + t * 4, wp + t * 4);
    cp_commit();
    load_stage<128>(A,  Ab, wp, 256,   16640, t);  cp_commit();
    load_stage<128>(Bf, Bb, wp, 16768, 33152, t);  cp_commit();

    while (true) {
        const int   e_next   = e + gridStride;
        const bool  has_next = (e_next < BATCH);
        const float* wpn     = fw + (size_t)e_next * TP;

        // L0 (reads S)
        cp_wait<2>(); __syncthreads();
        {
            float xb = x[e];
            float z  = fmaf(xb, S[t], S[128 + t]);
            y[t] = silu(z);
        }
        __syncthreads();

        // L1 (reads A)
        cp_wait<1>(); __syncthreads();
        {
            float z = dense_row<128>(A, Ab, y, t);
            __syncthreads();
            y[t] = silu(z);
            __syncthreads();
        }
        load_stage<128>(A, Ab, wp, 33280, 49664, t);  cp_commit();   // s3 -> A

        // L2 (reads B)
        cp_wait<1>(); __syncthreads();
        {
            float z = dense_row<128>(Bf, Bb, y, t);
            __syncthreads();
            y[t] = silu(z);
            __syncthreads();
        }
        load_stage<64>(Bf, Bb, wp, 49792, 57984, t);  cp_commit();   // s4 -> B

        // L3 (reads A)
        cp_wait<1>(); __syncthreads();
        {
            float z = dense_row<128>(A, Ab, y, t);
            __syncthreads();
            y[t] = silu(z);
            __syncthreads();
        }
        if (has_next) {
            if (t < 64) cp16(S + t * 4, wpn + t * 4);                 // s0(e+1)
            cp_commit();
            load_stage<128>(A, Ab, wpn, 256, 16640, t);  cp_commit(); // s1(e+1)
        }

        // L4 + head (reads B)
        if (has_next) cp_wait<2>(); else cp_wait<0>();
        __syncthreads();
        if (t < 64) {
            float z = dense_row<64>(Bf, Bb, y, t);
            float o;
            if (t < 32) {
                o = tanhf(z);
            } else {
                float lv = fminf(fmaxf(z, -4.0f), 4.0f);
                o = __expf(0.5f * lv);
            }
            out[(size_t)e * 64 + t] = o;
        }
        __syncthreads();

        if (!has_next) break;
        load_stage<128>(Bf, Bb, wpn, 16768, 33152, t);  cp_commit();  // s2(e+1)
        e  = e_next;
        wp = wpn;
    }
}

extern "C" void kernel_launch(void* const* d_in, const int* in_sizes, int n_in,
                              void* d_out, int out_size) {
    // Defensive input selection by element count (sizes differ by ~4 orders
    // of magnitude, so this is exact): x has BATCH elems, fw has BATCH*TP.
    const float* x  = (const float*)d_in[0];
    const float* fw = (const float*)d_in[1];
    if (n_in >= 2 && in_sizes[0] > in_sizes[1]) {
        fw = (const float*)d_in[0];
        x  = (const float*)d_in[1];
    }
    float* out = (float*)d_out;                // [4096, 64] fp32

    const size_t smem = (size_t)(256 + 128 + 2 * ABUF_FLTS) * sizeof(float); // 137,728 B

    int dev = 0;
    cudaGetDevice(&dev);
    int sms = 148;
    cudaDeviceGetAttribute(&sms, cudaDevAttrMultiProcessorCount, dev);
    cudaFuncSetAttribute(rootmlp_kernel,
                         cudaFuncAttributeMaxDynamicSharedMemorySize, (int)smem);

    int grid = sms;
    if (grid > BATCH) grid = BATCH;

    rootmlp_kernel<<<grid, 128, smem>>>(x, fw, out, grid);
}